// round 16
// baseline (speedup 1.0000x reference)
#include <cuda_runtime.h>
#include <math.h>

#define NQ 16
#define DIM 65536
#define BATCH 64
#define NC 23

__device__ float4 g_state4[BATCH * DIM / 2];   // 32 MB state, normal layout
__device__ float2 g_U[2][BATCH][NQ][4];        // fused Rot@RX per layer/sample/wire
__device__ float2 g_crx[2][NQ];                // (cos(th/2), sin(th/2))
__device__ float  g_partial[BATCH][8][16];

#define PD(i) ((i) + ((i) >> 4))
#define SMEM_F2 8704
#define SMEM_BYTES (SMEM_F2 * 8)

__device__ __forceinline__ float2 cmul(float2 a, float2 b) {
    return make_float2(a.x * b.x - a.y * b.y, a.x * b.y + a.y * b.x);
}
__device__ __forceinline__ void umix(float2& a0, float2& a1,
                                     float2 u0, float2 u1, float2 u2, float2 u3) {
    float2 n0, n1;
    n0.x = u0.x * a0.x - u0.y * a0.y + u1.x * a1.x - u1.y * a1.y;
    n0.y = u0.x * a0.y + u0.y * a0.x + u1.x * a1.y + u1.y * a1.x;
    n1.x = u2.x * a0.x - u2.y * a0.y + u3.x * a1.x - u3.y * a1.y;
    n1.y = u2.x * a0.y + u2.y * a0.x + u3.x * a1.y + u3.y * a1.x;
    a0 = n0; a1 = n1;
}
// RX pair mix applied under control=1: RX=[[c,-is],[-is,c]]
__device__ __forceinline__ void crxmix(float2& a0, float2& a1, float c, float s) {
    float2 n0 = make_float2(c * a0.x + s * a1.y, c * a0.y - s * a1.x);
    float2 n1 = make_float2(s * a0.y + c * a1.x, -s * a0.x + c * a1.y);
    a0 = n0; a1 = n1;
}

// ---------------- P0: fused U = Rot @ RX, CRX tables ------------------------
__global__ void k_prep(const float* __restrict__ x, const float* __restrict__ w0,
                       const float* __restrict__ x0, const float* __restrict__ w1,
                       const float* __restrict__ x1) {
    int t = blockIdx.x * blockDim.x + threadIdx.x;
    if (t < 2 * NQ) {
        int l = t >> 4, q = t & 15;
        float th = 0.5f * (l == 0 ? x0[q] : x1[q]);
        g_crx[l][q] = make_float2(cosf(th), sinf(th));
    }
    if (t < 2 * BATCH * NQ) {
        int l = t / (BATCH * NQ);
        int r = t % (BATCH * NQ);
        int b = r / NQ, q = r % NQ;
        float hx = 0.5f * x[b * NQ + q];
        float cx = cosf(hx), sx = sinf(hx);
        const float* w = (l == 0 ? w0 : w1) + q * 3;
        float phi = w[0], th = w[1], om = w[2];
        float ct = cosf(0.5f * th), st = sinf(0.5f * th);
        float ap = 0.5f * (phi + om), am = 0.5f * (phi - om);
        float cap = cosf(ap), sap = sinf(ap), cam = cosf(am), sam = sinf(am);
        float2 a  = make_float2(cap * ct, -sap * ct);
        float2 bb = make_float2(-cam * st, -sam * st);
        float2 cc = make_float2(cam * st, -sam * st);
        float2 d  = make_float2(cap * ct,  sap * ct);
        g_U[l][b][q][0] = make_float2(a.x * cx + bb.y * sx,  a.y * cx - bb.x * sx);
        g_U[l][b][q][1] = make_float2(a.y * sx + bb.x * cx, -a.x * sx + bb.y * cx);
        g_U[l][b][q][2] = make_float2(cc.x * cx + d.y * sx,  cc.y * cx - d.x * sx);
        g_U[l][b][q][3] = make_float2(cc.y * sx + d.x * cx, -cc.x * sx + d.y * cx);
    }
}

// ---------------- generic window gate helpers --------------------------------
template<int H, int L>
__device__ __forceinline__ void applyCRX(float2* r, float2 cs) {
    #pragma unroll
    for (int j = 0; j < 16; j++)
        if (((j >> H) & 1) && !((j >> L) & 1))
            crxmix(r[j], r[j | (1 << L)], cs.x, cs.y);
}
template<int K>
__device__ __forceinline__ void applyU(float2* r, const float2* __restrict__ gu) {
    float2 u0 = gu[0], u1 = gu[1], u2 = gu[2], u3 = gu[3];
    #pragma unroll
    for (int j = 0; j < 16; j++)
        if (!((j >> K) & 1))
            umix(r[j], r[j | (1 << K)], u0, u1, u2, u3);
}
// gates of a chain window (registers): optional pre-RX on w3, CRX q,q+1,q+2,
// optional U wires on w3,w2,w1.
__device__ __forceinline__ void win_gates(float2* r, int lr, int q,
                                          const float2* uw0, const float2* uw1,
                                          const float2* uw2, bool dopre, int preq) {
    if (dopre) {
        float2 cs = g_crx[lr][preq];
        #pragma unroll
        for (int j = 0; j < 8; j++) crxmix(r[j], r[j | 8], cs.x, cs.y);
    }
    applyCRX<3, 2>(r, g_crx[lr][q]);
    applyCRX<2, 1>(r, g_crx[lr][q + 1]);
    applyCRX<1, 0>(r, g_crx[lr][q + 2]);
    if (uw0) {
        applyU<3>(r, uw0);
        applyU<2>(r, uw1);
        applyU<1>(r, uw2);
    }
}

// contiguous 4-bit window over local bits [SH, SH+3]; constant-folded PD offsets.
template<int SH>
__device__ __forceinline__ void window_chainT(float2* s, int v, int lr, int q,
                                              const float2* uw0, const float2* uw1,
                                              const float2* uw2, bool dopre, int preq) {
    int base = ((v >> SH) << (SH + 4)) | (v & ((1 << SH) - 1));
    int pb = base + (base >> 4);
    float2 r[16];
    #pragma unroll
    for (int j = 0; j < 16; j++) {
        const int off = (j << SH) + ((j << SH) >> 4);
        r[j] = s[pb + off];
    }
    win_gates(r, lr, q, uw0, uw1, uw2, dopre, preq);
    #pragma unroll
    for (int j = 0; j < 16; j++) {
        const int off = (j << SH) + ((j << SH) >> 4);
        s[pb + off] = r[j];
    }
}

// ------- P1: chain0 — fused generate+window<9>, windows 6,3, then fused
//         window<0>+global-store.  Block owns j bits 0..12; chunk = j[13..15].
__global__ __launch_bounds__(256) void k_chain0() {
    extern __shared__ float2 s[];
    __shared__ float2 A[256], Bv[32], f[16][2];
    int b = blockIdx.y, tid = threadIdx.x, chunk = blockIdx.x;
    if (tid < 32) f[tid >> 1][tid & 1] = g_U[0][b][15 - (tid >> 1)][(tid & 1) * 2];
    __syncthreads();
    {   // A: product over bits 0..7
        float2 c = f[0][tid & 1];
        #pragma unroll
        for (int j = 1; j <= 7; j++) c = cmul(c, f[j][(tid >> j) & 1]);
        A[tid] = c;
    }
    if (tid < 32) {
        float2 c = f[8][tid & 1];
        #pragma unroll
        for (int j = 9; j <= 12; j++) c = cmul(c, f[j][(tid >> (j - 8)) & 1]);
        float2 F[8];
        #pragma unroll
        for (int i = 0; i < 8; i++)
            F[i] = cmul(cmul(f[13][i & 1], f[14][(i >> 1) & 1]), f[15][(i >> 2) & 1]);
        float2 cs = g_crx[0][0];                      // q0: ctrl b15 -> tgt b14
        crxmix(F[4], F[6], cs.x, cs.y); crxmix(F[5], F[7], cs.x, cs.y);
        cs = g_crx[0][1];                             // q1: ctrl b14 -> tgt b13
        crxmix(F[2], F[3], cs.x, cs.y); crxmix(F[6], F[7], cs.x, cs.y);
        Bv[tid] = cmul(c, F[chunk]);
    }
    __syncthreads();
    bool doq2 = (chunk & 1);                          // j13 == 1
    // fused generate + window sh=9 (two instances): m = v | (j<<9)
    #pragma unroll
    for (int inst = 0; inst < 2; inst++) {
        int v = tid + (inst << 8);                    // 0..511
        float2 a = A[v & 255];
        float2 r[16];
        #pragma unroll
        for (int j = 0; j < 16; j++) r[j] = cmul(a, Bv[(v >> 8) | (j << 1)]);
        win_gates(r, 0, 3, &g_U[1][b][3][0], &g_U[1][b][4][0], &g_U[1][b][5][0], doq2, 2);
        int pdv = v + (v >> 4);
        #pragma unroll
        for (int j = 0; j < 16; j++) s[pdv + j * 544] = r[j];
    }
    __syncthreads();
    window_chainT<6>(s, tid,       0, 6, &g_U[1][b][6][0], &g_U[1][b][7][0], &g_U[1][b][8][0], false, 0);
    window_chainT<6>(s, tid + 256, 0, 6, &g_U[1][b][6][0], &g_U[1][b][7][0], &g_U[1][b][8][0], false, 0);
    __syncthreads();
    window_chainT<3>(s, tid,       0, 9, &g_U[1][b][9][0], &g_U[1][b][10][0], &g_U[1][b][11][0], false, 0);
    window_chainT<3>(s, tid + 256, 0, 9, &g_U[1][b][9][0], &g_U[1][b][10][0], &g_U[1][b][11][0], false, 0);
    __syncthreads();
    // fused window<0> + global store: amps m = (v<<4)+j are 16 consecutive f2
    float4* g4 = g_state4 + (size_t)b * 32768 + (size_t)chunk * 4096;
    #pragma unroll
    for (int inst = 0; inst < 2; inst++) {
        int v = tid + (inst << 8);                    // 0..511
        float2 r[16];
        #pragma unroll
        for (int j = 0; j < 16; j++) r[j] = s[17 * v + j];   // PD((v<<4)+j)=17v+j
        win_gates(r, 0, 12, &g_U[1][b][12][0], &g_U[1][b][13][0], &g_U[1][b][14][0], false, 0);
        #pragma unroll
        for (int k = 0; k < 8; k++)
            g4[8 * v + k] = make_float4(r[2 * k].x, r[2 * k].y, r[2 * k + 1].x, r[2 * k + 1].y);
    }
}

// ------- P2: k_bnd2 — owns j bits {15,14,13,12}; chunk over j[0..11].
// Gates: L1 wrap q15 (cond on b0 = t&1); L2 U wires 0,1,2; L2 CRX q0,q1,q2.
__global__ __launch_bounds__(256, 4) void k_bnd2() {
    int b = blockIdx.y;
    int t = blockIdx.x * blockDim.x + threadIdx.x;   // 0..4095 = j[0..11]
    float2* g2 = (float2*)g_state4 + (size_t)b * DIM;
    float2 r[16];                                    // i = (b15<<3)|(b14<<2)|(b13<<1)|b12
    #pragma unroll
    for (int i = 0; i < 16; i++) r[i] = g2[t | (i << 12)];
    if (t & 1) {                                     // L1 q15: RX on b15 (ctrl b0=1)
        float2 cs = g_crx[0][15];
        #pragma unroll
        for (int i = 0; i < 8; i++) crxmix(r[i], r[i + 8], cs.x, cs.y);
    }
    applyU<3>(r, &g_U[1][b][0][0]);                  // U wire0 @ b15
    applyU<2>(r, &g_U[1][b][1][0]);                  // U wire1 @ b14
    applyU<1>(r, &g_U[1][b][2][0]);                  // U wire2 @ b13
    {   // L2 q0: ctrl b15 -> tgt b14
        float2 cs = g_crx[1][0];
        crxmix(r[8], r[12], cs.x, cs.y);  crxmix(r[9], r[13], cs.x, cs.y);
        crxmix(r[10], r[14], cs.x, cs.y); crxmix(r[11], r[15], cs.x, cs.y);
    }
    {   // L2 q1: ctrl b14 -> tgt b13
        float2 cs = g_crx[1][1];
        crxmix(r[4], r[6], cs.x, cs.y);   crxmix(r[5], r[7], cs.x, cs.y);
        crxmix(r[12], r[14], cs.x, cs.y); crxmix(r[13], r[15], cs.x, cs.y);
    }
    {   // L2 q2: ctrl b13 -> tgt b12
        float2 cs = g_crx[1][2];
        crxmix(r[2], r[3], cs.x, cs.y);   crxmix(r[6], r[7], cs.x, cs.y);
        crxmix(r[10], r[11], cs.x, cs.y); crxmix(r[14], r[15], cs.x, cs.y);
    }
    #pragma unroll
    for (int i = 0; i < 16; i++) g2[t | (i << 12)] = r[i];
}

// ------- P3: k_chain1m — owns j bits {0..11,15}; chunk = j[12..14].
// Fused global-load+window<8> (q3 cond,q4,q5,q6), windows 5,2, final window
// {b0,b1,b2,j15}: U15, q13, q14, wrap q15 + fused signed |amp|^2 reduction.
__global__ __launch_bounds__(256) void k_chain1m() {
    extern __shared__ float2 s[];
    int b = blockIdx.y, chunk = blockIdx.x, tid = threadIdx.x;
    const float2* g2 = (const float2*)g_state4 + (size_t)b * DIM;
    bool doq3 = (chunk & 1);                         // b12 == 1
    // fused load + window sh=8: m = base + (j<<8), base = ((v>>8)<<12)|(v&255)
    #pragma unroll
    for (int inst = 0; inst < 2; inst++) {
        int v = tid + (inst << 8);                   // 0..511
        float2 r[16];
        int glo = (v & 255) | (chunk << 12) | ((v >> 8) << 15);
        #pragma unroll
        for (int j = 0; j < 16; j++) r[j] = g2[glo | (j << 8)];
        win_gates(r, 1, 4, 0, 0, 0, doq3, 3);        // q3(cond),q4,q5,q6
        int base = ((v >> 8) << 12) | (v & 255);
        int pdb = base + (base >> 4);
        #pragma unroll
        for (int j = 0; j < 16; j++) s[pdb + j * 272] = r[j];
    }
    __syncthreads();
    window_chainT<5>(s, tid,       1, 7, 0, 0, 0, false, 0);  // q7,q8,q9
    window_chainT<5>(s, tid + 256, 1, 7, 0, 0, 0, false, 0);
    __syncthreads();
    window_chainT<2>(s, tid,       1, 10, 0, 0, 0, false, 0); // q10,q11,q12
    window_chainT<2>(s, tid + 256, 1, 10, 0, 0, 0, false, 0);
    __syncthreads();
    // final window: i = (j15<<3)|(b2<<2)|(b1<<1)|b0; free = b3..b11 (9 bits)
    float sums[16];
    #pragma unroll
    for (int w = 0; w < 16; w++) sums[w] = 0.f;
    float Tc = 0.f;
    const float2* gu = &g_U[1][b][15][0];
    float2 u0 = gu[0], u1 = gu[1], u2 = gu[2], u3 = gu[3];
    float2 c13 = g_crx[1][13], c14 = g_crx[1][14], c15 = g_crx[1][15];
    #pragma unroll
    for (int k = 0; k < 2; k++) {
        int v = tid + (k << 8);                      // 0..511
        int pvb = (v << 3) + (v >> 1);               // PD(v<<3)
        float2 r[16];
        #pragma unroll
        for (int i = 0; i < 16; i++) {
            const int off = (i & 7) + ((i >> 3) << 12) + ((i >> 3) << 8);
            r[i] = s[pvb + off];
        }
        #pragma unroll
        for (int i = 0; i < 16; i += 2)              // U wire15 @ b0
            umix(r[i], r[i + 1], u0, u1, u2, u3);
        // q13: ctrl b2 -> tgt b1
        crxmix(r[4], r[6], c13.x, c13.y);   crxmix(r[5], r[7], c13.x, c13.y);
        crxmix(r[12], r[14], c13.x, c13.y); crxmix(r[13], r[15], c13.x, c13.y);
        // q14: ctrl b1 -> tgt b0
        crxmix(r[2], r[3], c14.x, c14.y);   crxmix(r[6], r[7], c14.x, c14.y);
        crxmix(r[10], r[11], c14.x, c14.y); crxmix(r[14], r[15], c14.x, c14.y);
        // q15 wrap: ctrl b0 -> tgt j15
        crxmix(r[1], r[9], c15.x, c15.y);   crxmix(r[3], r[11], c15.x, c15.y);
        crxmix(r[5], r[13], c15.x, c15.y);  crxmix(r[7], r[15], c15.x, c15.y);
        float p[16];
        #pragma unroll
        for (int i = 0; i < 16; i++) p[i] = r[i].x * r[i].x + r[i].y * r[i].y;
        float T = 0.f;
        #pragma unroll
        for (int i = 0; i < 16; i++) T += p[i];
        float S3 = p[8] + p[9] + p[10] + p[11] + p[12] + p[13] + p[14] + p[15]; // j15=1
        float S2 = p[4] + p[5] + p[6] + p[7] + p[12] + p[13] + p[14] + p[15];   // b2=1
        float S1 = p[2] + p[3] + p[6] + p[7] + p[10] + p[11] + p[14] + p[15];   // b1=1
        float S0 = p[1] + p[3] + p[5] + p[7] + p[9] + p[11] + p[13] + p[15];    // b0=1
        sums[0]  += T - 2.f * S3;                    // wire0  <- j15
        sums[13] += T - 2.f * S2;                    // wire13 <- b2
        sums[14] += T - 2.f * S1;                    // wire14 <- b1
        sums[15] += T - 2.f * S0;                    // wire15 <- b0
        Tc += T;
        #pragma unroll
        for (int w = 4; w <= 12; w++)                // wire w <- b(15-w)
            sums[w] += ((v >> (12 - w)) & 1) ? -T : T;
    }
    sums[1] = (chunk & 4) ? -Tc : Tc;                // wire1 <- b14
    sums[2] = (chunk & 2) ? -Tc : Tc;                // wire2 <- b13
    sums[3] = (chunk & 1) ? -Tc : Tc;                // wire3 <- b12
    __syncthreads();
    float* sf = (float*)s;                           // 256*17 floats << smem
    #pragma unroll
    for (int w = 0; w < 16; w++) sf[tid * 17 + w] = sums[w];
    __syncthreads();
    int wd = tid >> 5, ln = tid & 31;                // 8 warps, 2 wires each
    #pragma unroll
    for (int rep = 0; rep < 2; rep++) {
        int w = wd * 2 + rep;
        float vv = 0.f;
        #pragma unroll
        for (int k = 0; k < 8; k++) vv += sf[(ln + (k << 5)) * 17 + w];
        #pragma unroll
        for (int o = 16; o; o >>= 1) vv += __shfl_xor_sync(0xffffffffu, vv, o);
        if (ln == 0) g_partial[b][chunk][w] = vv;
    }
}

// ---------------- P4: FC + log_softmax --------------------------------------
__global__ void k_head(const float* __restrict__ fc_w, const float* __restrict__ fc_b,
                       float* __restrict__ out) {
    int b = blockIdx.x, lane = threadIdx.x;
    __shared__ float feats[16];
    if (lane < 16) {
        float v = 0.f;
        #pragma unroll
        for (int k = 0; k < 8; k++) v += g_partial[b][k][lane];
        feats[lane] = v;
    }
    __syncthreads();
    float logit = -1e30f;
    if (lane < NC) {
        float v = fc_b[lane];
        #pragma unroll
        for (int w = 0; w < 16; w++) v += feats[w] * fc_w[lane * 16 + w];
        logit = v;
    }
    float m = logit;
    #pragma unroll
    for (int o = 16; o; o >>= 1) m = fmaxf(m, __shfl_xor_sync(0xffffffffu, m, o));
    float e = (lane < NC) ? expf(logit - m) : 0.f;
    #pragma unroll
    for (int o = 16; o; o >>= 1) e += __shfl_xor_sync(0xffffffffu, e, o);
    float lse = m + logf(e);
    if (lane < NC) out[b * NC + lane] = logit - lse;
}

extern "C" void kernel_launch(void* const* d_in, const int* in_sizes, int n_in,
                              void* d_out, int out_size) {
    const float* x    = (const float*)d_in[0];
    const float* w0   = (const float*)d_in[1];
    const float* x0   = (const float*)d_in[2];
    const float* w1   = (const float*)d_in[3];
    const float* x1   = (const float*)d_in[4];
    const float* fc_w = (const float*)d_in[5];
    const float* fc_b = (const float*)d_in[6];
    float* out = (float*)d_out;

    cudaFuncSetAttribute(k_chain0,  cudaFuncAttributeMaxDynamicSharedMemorySize, SMEM_BYTES);
    cudaFuncSetAttribute(k_chain1m, cudaFuncAttributeMaxDynamicSharedMemorySize, SMEM_BYTES);

    k_prep<<<8, 256>>>(x, w0, x0, w1, x1);
    k_chain0<<<dim3(8, BATCH), 256, SMEM_BYTES>>>();
    k_bnd2<<<dim3(16, BATCH), 256>>>();
    k_chain1m<<<dim3(8, BATCH), 256, SMEM_BYTES>>>();
    k_head<<<BATCH, 32>>>(fc_w, fc_b, out);
}

// round 17
// speedup vs baseline: 1.0813x; 1.0813x over previous
#include <cuda_runtime.h>
#include <math.h>

#define NQ 16
#define DIM 65536
#define BATCH 64
#define NC 23

__device__ float4 g_state4[BATCH * DIM / 2];   // 32 MB state, normal layout
__device__ float2 g_U[2][BATCH][NQ][4];        // fused Rot@RX per layer/sample/wire
__device__ float2 g_crx[2][NQ];                // (cos(th/2), sin(th/2))
__device__ float  g_partial[BATCH][8][16];
__device__ int    g_ticket[BATCH];

#define PD(i) ((i) + ((i) >> 4))
#define SMEM_F2 8704
#define SMEM_BYTES (SMEM_F2 * 8)

__device__ __forceinline__ float2 cmul(float2 a, float2 b) {
    return make_float2(a.x * b.x - a.y * b.y, a.x * b.y + a.y * b.x);
}
__device__ __forceinline__ void umix(float2& a0, float2& a1,
                                     float2 u0, float2 u1, float2 u2, float2 u3) {
    float2 n0, n1;
    n0.x = u0.x * a0.x - u0.y * a0.y + u1.x * a1.x - u1.y * a1.y;
    n0.y = u0.x * a0.y + u0.y * a0.x + u1.x * a1.y + u1.y * a1.x;
    n1.x = u2.x * a0.x - u2.y * a0.y + u3.x * a1.x - u3.y * a1.y;
    n1.y = u2.x * a0.y + u2.y * a0.x + u3.x * a1.y + u3.y * a1.x;
    a0 = n0; a1 = n1;
}
// RX pair mix applied under control=1: RX=[[c,-is],[-is,c]]
__device__ __forceinline__ void crxmix(float2& a0, float2& a1, float c, float s) {
    float2 n0 = make_float2(c * a0.x + s * a1.y, c * a0.y - s * a1.x);
    float2 n1 = make_float2(s * a0.y + c * a1.x, -s * a0.x + c * a1.y);
    a0 = n0; a1 = n1;
}

// ---------------- P0: fused U = Rot @ RX, CRX tables, ticket reset ----------
__global__ void k_prep(const float* __restrict__ x, const float* __restrict__ w0,
                       const float* __restrict__ x0, const float* __restrict__ w1,
                       const float* __restrict__ x1) {
    int t = blockIdx.x * blockDim.x + threadIdx.x;
    if (t < BATCH) g_ticket[t] = 0;
    if (t < 2 * NQ) {
        int l = t >> 4, q = t & 15;
        float th = 0.5f * (l == 0 ? x0[q] : x1[q]);
        g_crx[l][q] = make_float2(cosf(th), sinf(th));
    }
    if (t < 2 * BATCH * NQ) {
        int l = t / (BATCH * NQ);
        int r = t % (BATCH * NQ);
        int b = r / NQ, q = r % NQ;
        float hx = 0.5f * x[b * NQ + q];
        float cx = cosf(hx), sx = sinf(hx);
        const float* w = (l == 0 ? w0 : w1) + q * 3;
        float phi = w[0], th = w[1], om = w[2];
        float ct = cosf(0.5f * th), st = sinf(0.5f * th);
        float ap = 0.5f * (phi + om), am = 0.5f * (phi - om);
        float cap = cosf(ap), sap = sinf(ap), cam = cosf(am), sam = sinf(am);
        float2 a  = make_float2(cap * ct, -sap * ct);
        float2 bb = make_float2(-cam * st, -sam * st);
        float2 cc = make_float2(cam * st, -sam * st);
        float2 d  = make_float2(cap * ct,  sap * ct);
        g_U[l][b][q][0] = make_float2(a.x * cx + bb.y * sx,  a.y * cx - bb.x * sx);
        g_U[l][b][q][1] = make_float2(a.y * sx + bb.x * cx, -a.x * sx + bb.y * cx);
        g_U[l][b][q][2] = make_float2(cc.x * cx + d.y * sx,  cc.y * cx - d.x * sx);
        g_U[l][b][q][3] = make_float2(cc.y * sx + d.x * cx, -cc.x * sx + d.y * cx);
    }
}

// ---------------- generic window gate helpers --------------------------------
template<int H, int L>
__device__ __forceinline__ void applyCRX(float2* r, float2 cs) {
    #pragma unroll
    for (int j = 0; j < 16; j++)
        if (((j >> H) & 1) && !((j >> L) & 1))
            crxmix(r[j], r[j | (1 << L)], cs.x, cs.y);
}
template<int K>
__device__ __forceinline__ void applyU(float2* r, const float2* __restrict__ gu) {
    float2 u0 = gu[0], u1 = gu[1], u2 = gu[2], u3 = gu[3];
    #pragma unroll
    for (int j = 0; j < 16; j++)
        if (!((j >> K) & 1))
            umix(r[j], r[j | (1 << K)], u0, u1, u2, u3);
}
// gates of a chain window (registers): optional pre-RX on w3, CRX q,q+1,q+2,
// optional U wires on w3,w2,w1.
__device__ __forceinline__ void win_gates(float2* r, int lr, int q,
                                          const float2* uw0, const float2* uw1,
                                          const float2* uw2, bool dopre, int preq) {
    if (dopre) {
        float2 cs = g_crx[lr][preq];
        #pragma unroll
        for (int j = 0; j < 8; j++) crxmix(r[j], r[j | 8], cs.x, cs.y);
    }
    applyCRX<3, 2>(r, g_crx[lr][q]);
    applyCRX<2, 1>(r, g_crx[lr][q + 1]);
    applyCRX<1, 0>(r, g_crx[lr][q + 2]);
    if (uw0) {
        applyU<3>(r, uw0);
        applyU<2>(r, uw1);
        applyU<1>(r, uw2);
    }
}

// contiguous 4-bit window over local bits [SH, SH+3]; constant-folded PD offsets.
template<int SH>
__device__ __forceinline__ void window_chainT(float2* s, int v, int lr, int q,
                                              const float2* uw0, const float2* uw1,
                                              const float2* uw2, bool dopre, int preq) {
    int base = ((v >> SH) << (SH + 4)) | (v & ((1 << SH) - 1));
    int pb = base + (base >> 4);
    float2 r[16];
    #pragma unroll
    for (int j = 0; j < 16; j++) {
        const int off = (j << SH) + ((j << SH) >> 4);
        r[j] = s[pb + off];
    }
    win_gates(r, lr, q, uw0, uw1, uw2, dopre, preq);
    #pragma unroll
    for (int j = 0; j < 16; j++) {
        const int off = (j << SH) + ((j << SH) >> 4);
        s[pb + off] = r[j];
    }
}

// ------- P1: chain0 — fused generate+window<9>, then windows 6,3,0, store.
//         Block owns j bits 0..12; chunk = j[13..15].  256 threads × 2 inst.
__global__ __launch_bounds__(256) void k_chain0() {
    extern __shared__ float2 s[];
    __shared__ float2 A[256], Bv[32], f[16][2];
    int b = blockIdx.y, tid = threadIdx.x, chunk = blockIdx.x;
    if (tid < 32) f[tid >> 1][tid & 1] = g_U[0][b][15 - (tid >> 1)][(tid & 1) * 2];
    __syncthreads();
    {   // A: product over bits 0..7
        float2 c = f[0][tid & 1];
        #pragma unroll
        for (int j = 1; j <= 7; j++) c = cmul(c, f[j][(tid >> j) & 1]);
        A[tid] = c;
    }
    if (tid < 32) {
        float2 c = f[8][tid & 1];
        #pragma unroll
        for (int j = 9; j <= 12; j++) c = cmul(c, f[j][(tid >> (j - 8)) & 1]);
        float2 F[8];
        #pragma unroll
        for (int i = 0; i < 8; i++)
            F[i] = cmul(cmul(f[13][i & 1], f[14][(i >> 1) & 1]), f[15][(i >> 2) & 1]);
        float2 cs = g_crx[0][0];                      // q0: ctrl b15 -> tgt b14
        crxmix(F[4], F[6], cs.x, cs.y); crxmix(F[5], F[7], cs.x, cs.y);
        cs = g_crx[0][1];                             // q1: ctrl b14 -> tgt b13
        crxmix(F[2], F[3], cs.x, cs.y); crxmix(F[6], F[7], cs.x, cs.y);
        Bv[tid] = cmul(c, F[chunk]);
    }
    __syncthreads();
    bool doq2 = (chunk & 1);                          // j13 == 1
    // fused generate + window sh=9 (two instances): m = v | (j<<9)
    #pragma unroll
    for (int inst = 0; inst < 2; inst++) {
        int v = tid + (inst << 8);                    // 0..511
        float2 a = A[v & 255];
        float2 r[16];
        #pragma unroll
        for (int j = 0; j < 16; j++) r[j] = cmul(a, Bv[(v >> 8) | (j << 1)]);
        win_gates(r, 0, 3, &g_U[1][b][3][0], &g_U[1][b][4][0], &g_U[1][b][5][0], doq2, 2);
        int pdv = v + (v >> 4);
        #pragma unroll
        for (int j = 0; j < 16; j++) s[pdv + j * 544] = r[j];
    }
    __syncthreads();
    window_chainT<6>(s, tid,       0, 6, &g_U[1][b][6][0], &g_U[1][b][7][0], &g_U[1][b][8][0], false, 0);
    window_chainT<6>(s, tid + 256, 0, 6, &g_U[1][b][6][0], &g_U[1][b][7][0], &g_U[1][b][8][0], false, 0);
    __syncthreads();
    window_chainT<3>(s, tid,       0, 9, &g_U[1][b][9][0], &g_U[1][b][10][0], &g_U[1][b][11][0], false, 0);
    window_chainT<3>(s, tid + 256, 0, 9, &g_U[1][b][9][0], &g_U[1][b][10][0], &g_U[1][b][11][0], false, 0);
    __syncthreads();
    window_chainT<0>(s, tid,       0, 12, &g_U[1][b][12][0], &g_U[1][b][13][0], &g_U[1][b][14][0], false, 0);
    window_chainT<0>(s, tid + 256, 0, 12, &g_U[1][b][12][0], &g_U[1][b][13][0], &g_U[1][b][14][0], false, 0);
    __syncthreads();
    float4* g4 = g_state4 + (size_t)b * 32768 + (size_t)chunk * 4096;
    {   // PD(2p) = PD(2*tid) + k*544
        int pd2 = 2 * tid + ((2 * tid) >> 4);
        #pragma unroll
        for (int k = 0; k < 16; k++) {
            float2 lo = s[pd2 + k * 544], hi = s[pd2 + 1 + k * 544];
            g4[tid + (k << 8)] = make_float4(lo.x, lo.y, hi.x, hi.y);
        }
    }
}

// ------- P2: k_bnd2 — owns j bits {15,14,13,12}; chunk over j[0..11].
// Gates: L1 wrap q15 (cond on b0 = t&1); L2 U wires 0,1,2; L2 CRX q0,q1,q2.
__global__ __launch_bounds__(256, 4) void k_bnd2() {
    int b = blockIdx.y;
    int t = blockIdx.x * blockDim.x + threadIdx.x;   // 0..4095 = j[0..11]
    float2* g2 = (float2*)g_state4 + (size_t)b * DIM;
    float2 r[16];                                    // i = (b15<<3)|(b14<<2)|(b13<<1)|b12
    #pragma unroll
    for (int i = 0; i < 16; i++) r[i] = g2[t | (i << 12)];
    if (t & 1) {                                     // L1 q15: RX on b15 (ctrl b0=1)
        float2 cs = g_crx[0][15];
        #pragma unroll
        for (int i = 0; i < 8; i++) crxmix(r[i], r[i + 8], cs.x, cs.y);
    }
    applyU<3>(r, &g_U[1][b][0][0]);                  // U wire0 @ b15
    applyU<2>(r, &g_U[1][b][1][0]);                  // U wire1 @ b14
    applyU<1>(r, &g_U[1][b][2][0]);                  // U wire2 @ b13
    {   // L2 q0: ctrl b15 -> tgt b14
        float2 cs = g_crx[1][0];
        crxmix(r[8], r[12], cs.x, cs.y);  crxmix(r[9], r[13], cs.x, cs.y);
        crxmix(r[10], r[14], cs.x, cs.y); crxmix(r[11], r[15], cs.x, cs.y);
    }
    {   // L2 q1: ctrl b14 -> tgt b13
        float2 cs = g_crx[1][1];
        crxmix(r[4], r[6], cs.x, cs.y);   crxmix(r[5], r[7], cs.x, cs.y);
        crxmix(r[12], r[14], cs.x, cs.y); crxmix(r[13], r[15], cs.x, cs.y);
    }
    {   // L2 q2: ctrl b13 -> tgt b12
        float2 cs = g_crx[1][2];
        crxmix(r[2], r[3], cs.x, cs.y);   crxmix(r[6], r[7], cs.x, cs.y);
        crxmix(r[10], r[11], cs.x, cs.y); crxmix(r[14], r[15], cs.x, cs.y);
    }
    #pragma unroll
    for (int i = 0; i < 16; i++) g2[t | (i << 12)] = r[i];
}

// ------- P3: k_chain1m — owns j bits {0..11,15}; chunk = j[12..14].
// Fused global-load+window<8> (q3 cond,q4,q5,q6), windows 5,2, final window
// {b0,b1,b2,j15}: U15, q13, q14, wrap q15 + fused signed |amp|^2 reduction.
// Last block per sample also computes FC + log_softmax (ticket).
__global__ __launch_bounds__(256) void k_chain1m(const float* __restrict__ fc_w,
                                                 const float* __restrict__ fc_b,
                                                 float* __restrict__ out) {
    extern __shared__ float2 s[];
    __shared__ int s_last;
    int b = blockIdx.y, chunk = blockIdx.x, tid = threadIdx.x;
    const float2* g2 = (const float2*)g_state4 + (size_t)b * DIM;
    bool doq3 = (chunk & 1);                         // b12 == 1
    // fused load + window sh=8: m = base + (j<<8), base = ((v>>8)<<12)|(v&255)
    #pragma unroll
    for (int inst = 0; inst < 2; inst++) {
        int v = tid + (inst << 8);                   // 0..511
        float2 r[16];
        int glo = (v & 255) | (chunk << 12) | ((v >> 8) << 15);
        #pragma unroll
        for (int j = 0; j < 16; j++) r[j] = g2[glo | (j << 8)];
        win_gates(r, 1, 4, 0, 0, 0, doq3, 3);        // q3(cond),q4,q5,q6
        int base = ((v >> 8) << 12) | (v & 255);
        int pdb = base + (base >> 4);
        #pragma unroll
        for (int j = 0; j < 16; j++) s[pdb + j * 272] = r[j];
    }
    __syncthreads();
    window_chainT<5>(s, tid,       1, 7, 0, 0, 0, false, 0);  // q7,q8,q9
    window_chainT<5>(s, tid + 256, 1, 7, 0, 0, 0, false, 0);
    __syncthreads();
    window_chainT<2>(s, tid,       1, 10, 0, 0, 0, false, 0); // q10,q11,q12
    window_chainT<2>(s, tid + 256, 1, 10, 0, 0, 0, false, 0);
    __syncthreads();
    // final window: i = (j15<<3)|(b2<<2)|(b1<<1)|b0; free = b3..b11 (9 bits)
    float sums[16];
    #pragma unroll
    for (int w = 0; w < 16; w++) sums[w] = 0.f;
    float Tc = 0.f;
    const float2* gu = &g_U[1][b][15][0];
    float2 u0 = gu[0], u1 = gu[1], u2 = gu[2], u3 = gu[3];
    float2 c13 = g_crx[1][13], c14 = g_crx[1][14], c15 = g_crx[1][15];
    #pragma unroll
    for (int k = 0; k < 2; k++) {
        int v = tid + (k << 8);                      // 0..511
        int pvb = (v << 3) + (v >> 1);               // PD(v<<3)
        float2 r[16];
        #pragma unroll
        for (int i = 0; i < 16; i++) {
            const int off = (i & 7) + ((i >> 3) << 12) + ((i >> 3) << 8);
            r[i] = s[pvb + off];
        }
        #pragma unroll
        for (int i = 0; i < 16; i += 2)              // U wire15 @ b0
            umix(r[i], r[i + 1], u0, u1, u2, u3);
        // q13: ctrl b2 -> tgt b1
        crxmix(r[4], r[6], c13.x, c13.y);   crxmix(r[5], r[7], c13.x, c13.y);
        crxmix(r[12], r[14], c13.x, c13.y); crxmix(r[13], r[15], c13.x, c13.y);
        // q14: ctrl b1 -> tgt b0
        crxmix(r[2], r[3], c14.x, c14.y);   crxmix(r[6], r[7], c14.x, c14.y);
        crxmix(r[10], r[11], c14.x, c14.y); crxmix(r[14], r[15], c14.x, c14.y);
        // q15 wrap: ctrl b0 -> tgt j15
        crxmix(r[1], r[9], c15.x, c15.y);   crxmix(r[3], r[11], c15.x, c15.y);
        crxmix(r[5], r[13], c15.x, c15.y);  crxmix(r[7], r[15], c15.x, c15.y);
        float p[16];
        #pragma unroll
        for (int i = 0; i < 16; i++) p[i] = r[i].x * r[i].x + r[i].y * r[i].y;
        float T = 0.f;
        #pragma unroll
        for (int i = 0; i < 16; i++) T += p[i];
        float S3 = p[8] + p[9] + p[10] + p[11] + p[12] + p[13] + p[14] + p[15]; // j15=1
        float S2 = p[4] + p[5] + p[6] + p[7] + p[12] + p[13] + p[14] + p[15];   // b2=1
        float S1 = p[2] + p[3] + p[6] + p[7] + p[10] + p[11] + p[14] + p[15];   // b1=1
        float S0 = p[1] + p[3] + p[5] + p[7] + p[9] + p[11] + p[13] + p[15];    // b0=1
        sums[0]  += T - 2.f * S3;                    // wire0  <- j15
        sums[13] += T - 2.f * S2;                    // wire13 <- b2
        sums[14] += T - 2.f * S1;                    // wire14 <- b1
        sums[15] += T - 2.f * S0;                    // wire15 <- b0
        Tc += T;
        #pragma unroll
        for (int w = 4; w <= 12; w++)                // wire w <- b(15-w)
            sums[w] += ((v >> (12 - w)) & 1) ? -T : T;
    }
    sums[1] = (chunk & 4) ? -Tc : Tc;                // wire1 <- b14
    sums[2] = (chunk & 2) ? -Tc : Tc;                // wire2 <- b13
    sums[3] = (chunk & 1) ? -Tc : Tc;                // wire3 <- b12
    __syncthreads();
    float* sf = (float*)s;                           // 256*17 floats << smem
    #pragma unroll
    for (int w = 0; w < 16; w++) sf[tid * 17 + w] = sums[w];
    __syncthreads();
    int wd = tid >> 5, ln = tid & 31;                // 8 warps, 2 wires each
    #pragma unroll
    for (int rep = 0; rep < 2; rep++) {
        int w = wd * 2 + rep;
        float vv = 0.f;
        #pragma unroll
        for (int k = 0; k < 8; k++) vv += sf[(ln + (k << 5)) * 17 + w];
        #pragma unroll
        for (int o = 16; o; o >>= 1) vv += __shfl_xor_sync(0xffffffffu, vv, o);
        if (ln == 0) g_partial[b][chunk][w] = vv;
    }
    __syncthreads();
    // ---- ticket: the 8th block for sample b computes FC + log_softmax ----
    if (tid == 0) {
        __threadfence();
        s_last = (atomicAdd(&g_ticket[b], 1) == 7);
    }
    __syncthreads();
    if (s_last && tid < 32) {
        __shared__ float feats[16];
        if (tid < 16) {
            float v = 0.f;
            #pragma unroll
            for (int k = 0; k < 8; k++) v += g_partial[b][k][tid];
            feats[tid] = v;
        }
        __syncwarp();
        float logit = -1e30f;
        if (tid < NC) {
            float v = fc_b[tid];
            #pragma unroll
            for (int w = 0; w < 16; w++) v += feats[w] * fc_w[tid * 16 + w];
            logit = v;
        }
        float m = logit;
        #pragma unroll
        for (int o = 16; o; o >>= 1) m = fmaxf(m, __shfl_xor_sync(0xffffffffu, m, o));
        float e = (tid < NC) ? expf(logit - m) : 0.f;
        #pragma unroll
        for (int o = 16; o; o >>= 1) e += __shfl_xor_sync(0xffffffffu, e, o);
        float lse = m + logf(e);
        if (tid < NC) out[b * NC + tid] = logit - lse;
    }
}

extern "C" void kernel_launch(void* const* d_in, const int* in_sizes, int n_in,
                              void* d_out, int out_size) {
    const float* x    = (const float*)d_in[0];
    const float* w0   = (const float*)d_in[1];
    const float* x0   = (const float*)d_in[2];
    const float* w1   = (const float*)d_in[3];
    const float* x1   = (const float*)d_in[4];
    const float* fc_w = (const float*)d_in[5];
    const float* fc_b = (const float*)d_in[6];
    float* out = (float*)d_out;

    cudaFuncSetAttribute(k_chain0,  cudaFuncAttributeMaxDynamicSharedMemorySize, SMEM_BYTES);
    cudaFuncSetAttribute(k_chain1m, cudaFuncAttributeMaxDynamicSharedMemorySize, SMEM_BYTES);

    k_prep<<<8, 256>>>(x, w0, x0, w1, x1);
    k_chain0<<<dim3(8, BATCH), 256, SMEM_BYTES>>>();
    k_bnd2<<<dim3(16, BATCH), 256>>>();
    k_chain1m<<<dim3(8, BATCH), 256, SMEM_BYTES>>>(fc_w, fc_b, out);
}